// round 8
// baseline (speedup 1.0000x reference)
#include <cuda_runtime.h>
#include <math.h>

#define NFRAMES 480          // B(16) * STEPS(30)
#define KDIM    5625         // 75*75 pooled cells
#define NNEUR   54
#define NPAD    64
#define STEPS   30
#define BATCH   16
#define FT      8            // frames per fused block
#define CROWS   5            // pooled rows per chunk
#define CCELLS  (CROWS * 75) // 375 cells per chunk
#define NCHUNK  15           // 75 / CROWS

// -------- scratch (device globals; no allocation allowed) --------
__device__ float g_wT[KDIM * NPAD];                     // transposed padded weights ~1.44 MB
__device__ float g_partial[NCHUNK * NFRAMES * NNEUR];   // split-K partials
__device__ float g_frames[NFRAMES * NNEUR];             // merged FC outputs

// ================= 1) transpose weights: fc_w[54][5625] -> wT[5625][64] (zero-pad) =====
__global__ void wT_kernel(const float* __restrict__ fc_w) {
    int i = blockIdx.x * blockDim.x + threadIdx.x;
    if (i >= KDIM * NPAD) return;
    int k = i >> 6;
    int n = i & 63;
    g_wT[i] = (n < NNEUR) ? fc_w[n * KDIM + k] : 0.f;
}

// ================= 2) fused pool(8x8 avg) + FC =========================================
// grid (60, 15), 256 threads. Pool: batched __ldcs LDG stream (evict-first keeps wT in
// L2). smem tile f-MINOR so FC reads 8 frames with 2 LDS.128 broadcasts.
__global__ void fused_kernel(const float* __restrict__ x) {
    __shared__ __align__(16) float xp_s[CCELLS * FT];  // 12000 B, [cell][frame]
    __shared__ float red[4 * FT * NPAD];               //  8192 B

    const int tid = threadIdx.x;
    const int f0  = blockIdx.x * FT;
    const int pr0 = blockIdx.y * CROWS;
    const int k0  = blockIdx.y * CCELLS;       // global pooled-cell base

    for (int idx = tid; idx < FT * CCELLS; idx += 256) {
        int f  = idx / CCELLS;
        int c  = idx - f * CCELLS;
        int pr = c / 75;
        int pc = c - pr * 75;
        const float* p = x + ((size_t)(f0 + f) * 600 + (size_t)(pr0 + pr) * 8) * 600 + pc * 8;
        float s = 0.f;
#pragma unroll
        for (int r = 0; r < 8; r++) {
            float4 a = __ldcs((const float4*)(p + (size_t)r * 600));
            float4 b = __ldcs((const float4*)(p + (size_t)r * 600 + 4));
            s += ((a.x + a.y) + (a.z + a.w)) + ((b.x + b.y) + (b.z + b.w));
        }
        xp_s[c * FT + f] = s * (1.f / 64.f);
    }
    __syncthreads();

    const int n = tid & 63;
    const int g = tid >> 6;
    float acc[FT];
#pragma unroll
    for (int f = 0; f < FT; f++) acc[f] = 0.f;

    for (int p = g; p < CCELLS; p += 4) {
        float w = g_wT[(size_t)(k0 + p) * NPAD + n];       // coalesced 128B, L2-resident
        float4 xa = *(const float4*)&xp_s[p * FT];         // LDS.128 broadcast
        float4 xb = *(const float4*)&xp_s[p * FT + 4];
        acc[0] += xa.x * w;  acc[1] += xa.y * w;
        acc[2] += xa.z * w;  acc[3] += xa.w * w;
        acc[4] += xb.x * w;  acc[5] += xb.y * w;
        acc[6] += xb.z * w;  acc[7] += xb.w * w;
    }
#pragma unroll
    for (int f = 0; f < FT; f++)
        red[(g * FT + f) * NPAD + n] = acc[f];
    __syncthreads();

    for (int idx = tid; idx < FT * NPAD; idx += 256) {
        int f  = idx >> 6;
        int nn = idx & 63;
        float s = ((red[(0 * FT + f) * NPAD + nn] + red[(1 * FT + f) * NPAD + nn])
                +  (red[(2 * FT + f) * NPAD + nn] + red[(3 * FT + f) * NPAD + nn]));
        if (nn < NNEUR)
            g_partial[((size_t)blockIdx.y * NFRAMES + (f0 + f)) * NNEUR + nn] = s;
    }
}

// ================= 3) merge partials + bias (fixed order => deterministic) =============
__global__ void merge_kernel(const float* __restrict__ fc_b) {
    int i = blockIdx.x * blockDim.x + threadIdx.x;
    if (i >= NFRAMES * NNEUR) return;
    int n = i % NNEUR;
    float s = fc_b[n];
#pragma unroll
    for (int c = 0; c < NCHUNK; c++)
        s += g_partial[(size_t)c * (NFRAMES * NNEUR) + i];
    g_frames[i] = s;
}

// ================= 4) spike scan v3: 256 threads = 8 warps, 2 batches/warp =============
// Warp w: lanes 0-15 = batch 2w, lanes 16-31 = batch 2w+1. Each lane owns 4 neuron
// slots n = hl+16s (s<3 always active; s=3 active iff hl<6). Per-batch lateral sum =
// 4-shfl half-warp butterfly. One barrier/step over 8 warps; frames double-buffer
// prefetched from L2 one step ahead (off the critical path).
__global__ void __launch_bounds__(256) scan_kernel(
        const float* __restrict__ lw, const float* __restrict__ hw,
        float* __restrict__ out) {
    __shared__ __align__(16) float wr[2][8];

    const int tid  = threadIdx.x;            // 0..255
    const int w    = tid >> 5;
    const int lane = tid & 31;
    const int hl   = lane & 15;
    const int b    = 2 * w + (lane >> 4);
    const bool act3 = (hl < NNEUR - 48);     // slot 3: n = hl+48 < 54

    const float w0 = hw[0], w1 = hw[1], w2 = hw[2], w3 = hw[3];
    // per-slot lateral weights (slot 3 zeroed when inactive)
    float lwr[4][4];
#pragma unroll
    for (int s = 0; s < 4; s++) {
        int n = hl + 16 * s;
        bool a = (s < 3) || act3;
#pragma unroll
        for (int d = 0; d < 4; d++)
            lwr[s][d] = a ? lw[n * 4 + d] : 0.f;
    }

    const float* fbase = g_frames + b * STEPS * NNEUR;
    float fr[2][4];
#pragma unroll
    for (int s = 0; s < 4; s++)              // prefetch t=0
        fr[0][s] = ((s < 3) || act3) ? __ldg(fbase + hl + 16 * s) : 0.f;

    float h[4][4];                            // hist per slot
#pragma unroll
    for (int s = 0; s < 4; s++)
#pragma unroll
        for (int d = 0; d < 4; d++) h[s][d] = 0.f;
    float cnt[4] = {0.f, 0.f, 0.f, 0.f};

#pragma unroll
    for (int t = 0; t < STEPS; t++) {
        // prefetch next step's frames (off critical path, L2 hit)
        if (t + 1 < STEPS) {
            const float* row = fbase + (t + 1) * NNEUR;
#pragma unroll
            for (int s = 0; s < 4; s++)
                fr[(t + 1) & 1][s] = ((s < 3) || act3) ? __ldg(row + hl + 16 * s) : 0.f;
        }

        float hs[4], e[4];
#pragma unroll
        for (int s = 0; s < 4; s++) {
            hs[s] = h[s][0]*lwr[s][0] + h[s][1]*lwr[s][1] + h[s][2]*lwr[s][2] + h[s][3]*lwr[s][3];
            float hh = h[s][0]*w0 + h[s][1]*w1 + h[s][2]*w2 + h[s][3]*w3;
            bool a = (s < 3) || act3;
            e[s] = a ? expf(fr[t & 1][s] - hs[s] + hh) : 0.f;
        }

        // half-warp butterflies (xor 8,4,2,1 never crosses the 16-lane boundary)
        float v = (hs[0] + hs[1]) + (hs[2] + hs[3]);     // -> batch hsum
        float sl = (e[0] + e[1]) + (e[2] + e[3]);        // -> batch sum of e
        v += __shfl_xor_sync(0xffffffffu, v, 8);   sl += __shfl_xor_sync(0xffffffffu, sl, 8);
        v += __shfl_xor_sync(0xffffffffu, v, 4);   sl += __shfl_xor_sync(0xffffffffu, sl, 4);
        v += __shfl_xor_sync(0xffffffffu, v, 2);   sl += __shfl_xor_sync(0xffffffffu, sl, 2);
        v += __shfl_xor_sync(0xffffffffu, v, 1);   sl += __shfl_xor_sync(0xffffffffu, sl, 1);

        float ebb = expf(v);                             // exp(bsum) for own batch
        float r = ebb * sl;                              // own batch rate sum
        r += __shfl_xor_sync(0xffffffffu, r, 16);        // + other batch in this warp
        if (lane == 0) wr[t & 1][w] = r;
        __syncthreads();                                 // the only barrier per step

        const float4* w4 = (const float4*)wr[t & 1];
        float4 q0 = w4[0], q1 = w4[1];
        float tot = ((q0.x + q0.y) + (q0.z + q0.w)) + ((q1.x + q1.y) + (q1.z + q1.w));
        float thr = tot * (1.f / (BATCH * NNEUR));

#pragma unroll
        for (int s = 0; s < 4; s++) {
            float sp = (e[s] * ebb > thr) ? 1.f : 0.f;   // e==0 -> never spikes (thr>0)
            cnt[s] += sp;
            h[s][0] = h[s][1]; h[s][1] = h[s][2]; h[s][2] = h[s][3]; h[s][3] = sp;
        }
    }
#pragma unroll
    for (int s = 0; s < 4; s++) {
        if ((s < 3) || act3) {
            float c = cnt[s];
            out[b * NNEUR + hl + 16 * s] = c + log1pf(expf(-c));  // exact softplus, c>=0
        }
    }
}

// =======================================================================================
extern "C" void kernel_launch(void* const* d_in, const int* in_sizes, int n_in,
                              void* d_out, int out_size) {
    const float* x    = (const float*)d_in[0];
    const float* fc_w = (const float*)d_in[1];
    const float* fc_b = (const float*)d_in[2];
    const float* lw   = (const float*)d_in[3];
    const float* hw   = (const float*)d_in[4];
    float* out = (float*)d_out;

    wT_kernel<<<(KDIM * NPAD + 255) / 256, 256>>>(fc_w);
    fused_kernel<<<dim3(NFRAMES / FT, NCHUNK), 256>>>(x);
    merge_kernel<<<(NFRAMES * NNEUR + 255) / 256, 256>>>(fc_b);
    scan_kernel<<<1, 256>>>(lw, hw, out);
    (void)in_sizes; (void)n_in; (void)out_size;
}